// round 9
// baseline (speedup 1.0000x reference)
#include <cuda_runtime.h>
#include <cuda_fp16.h>

typedef unsigned int u32;

#define H 512
#define W 512
#define PLANE (H * W)
#define NPLANES 64          // 32 pred + 32 true planes (channel 1 only)
#define RB 16               // output rows per warp
#define BANDS (H / RB)      // 32
#define KSTEPS (RB + 8)     // 24 steps: two fused iterations need halo 4 rows
#define NBLOCKS (NPLANES * BANDS * 2 / 4)   // 1024 blocks of 128 thr

#define PINF2 0x7C007C00u
#define NINF2 0xFC00FC00u

__device__ __half g_bufA[(size_t)NPLANES * PLANE];   // 32 MB
__device__ __half g_bufB[(size_t)NPLANES * PLANE];   // 32 MB
__device__ double g_acc[4];  // cross_pred, sum_pred, cross_true, sum_true

__device__ __forceinline__ u32 h2min(u32 a, u32 b) {
    __half2 r = __hmin2(*reinterpret_cast<__half2*>(&a),
                        *reinterpret_cast<__half2*>(&b));
    return *reinterpret_cast<u32*>(&r);
}
__device__ __forceinline__ u32 h2max(u32 a, u32 b) {
    __half2 r = __hmax2(*reinterpret_cast<__half2*>(&a),
                        *reinterpret_cast<__half2*>(&b));
    return *reinterpret_cast<u32*>(&r);
}
__device__ __forceinline__ u32 h2sub(u32 a, u32 b) {
    __half2 r = __hsub2(*reinterpret_cast<__half2*>(&a),
                        *reinterpret_cast<__half2*>(&b));
    return *reinterpret_cast<u32*>(&r);
}
__device__ __forceinline__ u32 h2add(u32 a, u32 b) {
    __half2 r = __hadd2(*reinterpret_cast<__half2*>(&a),
                        *reinterpret_cast<__half2*>(&b));
    return *reinterpret_cast<u32*>(&r);
}
__device__ __forceinline__ u32 min3(u32 a, u32 b, u32 c) { return h2min(h2min(a, b), c); }
__device__ __forceinline__ u32 max3(u32 a, u32 b, u32 c) { return h2max(h2max(a, b), c); }
__device__ __forceinline__ u32 pk(float lo, float hi) {
    __half2 r = __floats2half2_rn(lo, hi);
    return *reinterpret_cast<u32*>(&r);
}
__device__ __forceinline__ float2 up(u32 v) {
    return __half22float2(*reinterpret_cast<__half2*>(&v));
}
// (a.hi, b.lo) as (lo, hi)
__device__ __forceinline__ u32 mid(u32 a, u32 b) { return __byte_perm(a, b, 0x5432); }
__device__ __forceinline__ u32 swp(u32 a)        { return __byte_perm(a, a, 0x1032); }

// TWO fused soft-skeletonize iterations per sweep. Pipeline per step:
//   load x row (depth-2 raw ring) -> expand to 8 u32 (halo +-4 cols)
//   iterA: vmin pair -> hmin -> hmax -> vmax pair -> zA (6 u32, halo +-2)
//   iterB: vmin pair -> hmin -> hmax -> vmax pair -> zB (4 u32, owned)
// EDGE=false for interior bands: all row-bounds predication compiles away.
// MODE 0: fp32 strided input. MODE 1: half->half. MODE 2: fused reduction.
template <int MODE, bool EDGE>
__device__ __forceinline__ void fused_core(
    int lane, int rbase, int cb, bool eL, bool eR,
    const float* __restrict__ chan, const __half* __restrict__ srcH,
    __half* __restrict__ dstH, const float* __restrict__ oth,
    float& accC_, float& accS_)
{
    u32 raw[3][4];      // raw loaded rows; row rbase-4+k in slot k%3
    u32 rawE[3][2];     // strip-edge halo (2 u32) per slot
    u32 xprev[8], xpair[8];       // iterA vertical-min pair state
    u32 xc1[6], xc2[6], mAc1[6];  // delayed centers for zA
    u32 hmpA[6], hmpairA[6];      // iterA vertical-max pair state
    u32 zprev[6], zpair[6];       // iterB vertical-min pair state
    u32 zAc1[4], zAc2[4], mBc1[4];
    u32 hmpB[4], hmpairB[4];      // iterB vertical-max pair state
    float accC = 0.f, accS = 0.f;

#pragma unroll
    for (int i = 0; i < 8; ++i) { xprev[i] = PINF2; xpair[i] = PINF2; }
#pragma unroll
    for (int i = 0; i < 6; ++i) {
        xc1[i] = 0u; xc2[i] = 0u; mAc1[i] = 0u;
        hmpA[i] = NINF2; hmpairA[i] = NINF2;
        zprev[i] = PINF2; zpair[i] = PINF2;
    }
#pragma unroll
    for (int i = 0; i < 4; ++i) {
        zAc1[i] = 0u; zAc2[i] = 0u; mBc1[i] = 0u;
        hmpB[i] = NINF2; hmpairB[i] = NINF2;
    }

    auto loadraw = [&](int r, int s) {
        u32 a0 = PINF2, a1 = PINF2, a2 = PINF2, a3 = PINF2;
        u32 e0 = PINF2, e1 = PINF2;
        if (!EDGE || (unsigned)r < H) {
            if (MODE == 0) {
                const float* row = chan + (size_t)r * W + cb;
                float4 f0 = *reinterpret_cast<const float4*>(row);
                float4 f1 = *reinterpret_cast<const float4*>(row + 4);
                a0 = pk(f0.x, f0.y); a1 = pk(f0.z, f0.w);
                a2 = pk(f1.x, f1.y); a3 = pk(f1.z, f1.w);
                if (eL) { float4 e = *reinterpret_cast<const float4*>(row - 4);
                          e0 = pk(e.x, e.y); e1 = pk(e.z, e.w); }
                else if (eR) { float4 e = *reinterpret_cast<const float4*>(row + 8);
                               e0 = pk(e.x, e.y); e1 = pk(e.z, e.w); }
            } else {
                const __half* row = srcH + (size_t)r * W + cb;
                uint4 v = *reinterpret_cast<const uint4*>(row);
                a0 = v.x; a1 = v.y; a2 = v.z; a3 = v.w;
                if (eL) { uint2 e = *reinterpret_cast<const uint2*>(row - 4);
                          e0 = e.x; e1 = e.y; }
                else if (eR) { uint2 e = *reinterpret_cast<const uint2*>(row + 8);
                               e0 = e.x; e1 = e.y; }
            }
        }
        raw[s][0] = a0; raw[s][1] = a1; raw[s][2] = a2; raw[s][3] = a3;
        rawE[s][0] = e0; rawE[s][1] = e1;
    };

    loadraw(rbase - 4, 0);
    loadraw(rbase - 3, 1);

#pragma unroll
    for (int k = 0; k < KSTEPS; ++k) {
        if (k < KSTEPS - 2) loadraw(rbase - 2 + k, (k + 2) % 3);

        // expand row rx = rbase-4+k (loaded 2 steps ago) to 8 u32
        u32 xn[8];
        {
            const int s = k % 3;
            u32 u2 = __shfl_up_sync(0xffffffffu, raw[s][2], 1);
            u32 u3 = __shfl_up_sync(0xffffffffu, raw[s][3], 1);
            u32 d0 = __shfl_down_sync(0xffffffffu, raw[s][0], 1);
            u32 d1 = __shfl_down_sync(0xffffffffu, raw[s][1], 1);
            if (lane == 0)  { u2 = eL ? rawE[s][0] : PINF2;
                              u3 = eL ? rawE[s][1] : PINF2; }
            if (lane == 31) { d0 = eR ? rawE[s][0] : PINF2;
                              d1 = eR ? rawE[s][1] : PINF2; }
            xn[0] = u2; xn[1] = u3;
            xn[2] = raw[s][0]; xn[3] = raw[s][1];
            xn[4] = raw[s][2]; xn[5] = raw[s][3];
            xn[6] = d0; xn[7] = d1;
        }

        // ===== iteration A =====
        // vertical min centered row rxm = rbase-5+k
        u32 vA[8];
#pragma unroll
        for (int i = 0; i < 8; ++i) vA[i] = h2min(xpair[i], xn[i]);
#pragma unroll
        for (int i = 0; i < 8; ++i) { xpair[i] = h2min(xprev[i], xn[i]); xprev[i] = xn[i]; }

        // horizontal min -> mA (8 u32, cols cb-4..cb+11, ends half-garbage)
        u32 pA[7];
#pragma unroll
        for (int i = 0; i < 7; ++i) pA[i] = mid(vA[i], vA[i + 1]);
        u32 mA[8];
        mA[0] = min3(swp(vA[0]), vA[0], pA[0]);
#pragma unroll
        for (int i = 1; i < 7; ++i) mA[i] = min3(pA[i - 1], vA[i], pA[i]);
        mA[7] = min3(pA[6], vA[7], swp(vA[7]));

        if (EDGE && (unsigned)(rbase - 5 + k) >= H) {
#pragma unroll
            for (int i = 0; i < 8; ++i) mA[i] = NINF2;
        }

        // horizontal max of mA -> hmA (6 u32, cols cb-2..cb+9)
        u32 qA[7];
#pragma unroll
        for (int i = 0; i < 7; ++i) qA[i] = mid(mA[i], mA[i + 1]);
        u32 hmA[6];
#pragma unroll
        for (int j = 0; j < 6; ++j) hmA[j] = max3(qA[j], mA[j + 1], qA[j + 1]);

        // vertical max pair -> dilA centered row rza = rbase-6+k
        u32 zA[6];
#pragma unroll
        for (int j = 0; j < 6; ++j) {
            u32 dil = h2max(hmpairA[j], hmA[j]);
            hmpairA[j] = h2max(hmpA[j], hmA[j]); hmpA[j] = hmA[j];
            // zA = relu(x - dil + m)   (dil >= m always)
            zA[j] = h2max(h2add(h2sub(xc2[j], dil), mAc1[j]), 0u);
        }
        if (EDGE && (unsigned)(rbase - 6 + k) >= H) {
#pragma unroll
            for (int j = 0; j < 6; ++j) zA[j] = PINF2;  // minpool pad for iterB
        }
#pragma unroll
        for (int j = 0; j < 6; ++j) { xc2[j] = xc1[j]; xc1[j] = xn[j + 1]; mAc1[j] = mA[j + 1]; }

        // ===== iteration B =====
        // vertical min centered row rzm = rbase-7+k
        u32 vB[6];
#pragma unroll
        for (int j = 0; j < 6; ++j) vB[j] = h2min(zpair[j], zA[j]);
#pragma unroll
        for (int j = 0; j < 6; ++j) { zpair[j] = h2min(zprev[j], zA[j]); zprev[j] = zA[j]; }

        // horizontal min -> mB (6 u32, cols cb-2..cb+9, valid cb-1..cb+8)
        u32 pB[5];
#pragma unroll
        for (int i = 0; i < 5; ++i) pB[i] = mid(vB[i], vB[i + 1]);
        u32 mB[6];
        mB[0] = min3(swp(vB[0]), vB[0], pB[0]);
#pragma unroll
        for (int i = 1; i < 5; ++i) mB[i] = min3(pB[i - 1], vB[i], pB[i]);
        mB[5] = min3(pB[4], vB[5], swp(vB[5]));

        if (EDGE && (unsigned)(rbase - 7 + k) >= H) {
#pragma unroll
            for (int i = 0; i < 6; ++i) mB[i] = NINF2;
        }

        // horizontal max of mB -> hmB (4 u32, owned cols)
        u32 qB[5];
#pragma unroll
        for (int i = 0; i < 5; ++i) qB[i] = mid(mB[i], mB[i + 1]);
        u32 hmB[4];
#pragma unroll
        for (int j = 0; j < 4; ++j) hmB[j] = max3(qB[j], mB[j + 1], qB[j + 1]);

        // vertical max pair -> dilB centered ro = rbase-8+k; then zB
        u32 dilB[4];
#pragma unroll
        for (int j = 0; j < 4; ++j) {
            dilB[j] = h2max(hmpairB[j], hmB[j]);
            hmpairB[j] = h2max(hmpB[j], hmB[j]); hmpB[j] = hmB[j];
        }

        if (k >= 8) {
            const int o = rbase - 8 + k;   // in [rbase, rbase+15]
            u32 z0 = h2max(h2add(h2sub(zAc2[0], dilB[0]), mBc1[0]), 0u);
            u32 z1 = h2max(h2add(h2sub(zAc2[1], dilB[1]), mBc1[1]), 0u);
            u32 z2 = h2max(h2add(h2sub(zAc2[2], dilB[2]), mBc1[2]), 0u);
            u32 z3 = h2max(h2add(h2sub(zAc2[3], dilB[3]), mBc1[3]), 0u);

            if (MODE == 2) {
                const float* orow = oth + (size_t)o * W + cb;
                float4 f0 = *reinterpret_cast<const float4*>(orow);
                float4 f1 = *reinterpret_cast<const float4*>(orow + 4);
                float2 a0 = up(z0), a1 = up(z1), a2 = up(z2), a3 = up(z3);
                accC += a0.x * f0.x + a0.y * f0.y + a1.x * f0.z + a1.y * f0.w;
                accC += a2.x * f1.x + a2.y * f1.y + a3.x * f1.z + a3.y * f1.w;
                accS += (a0.x + a0.y) + (a1.x + a1.y)
                      + (a2.x + a2.y) + (a3.x + a3.y);
            } else {
                uint4 st; st.x = z0; st.y = z1; st.z = z2; st.w = z3;
                *reinterpret_cast<uint4*>(dstH + (size_t)o * W + cb) = st;
            }
        }

#pragma unroll
        for (int j = 0; j < 4; ++j) {
            zAc2[j] = zAc1[j]; zAc1[j] = zA[j + 1]; mBc1[j] = mB[j + 1];
        }
    }

    accC_ = accC;
    accS_ = accS;
}

// MODE 0: iter pair (0,1), fp32 input -> bufA.
// MODE 1: iter pairs (2,3),(4,5),(6,7) half->half ping-pong.
// MODE 2: iter pair (8,9) + fused reduction.
template <int MODE>
__global__ void __launch_bounds__(128) skel2_kernel(
    const float* __restrict__ pred, const float* __restrict__ tru, int it)
{
    const int lane  = threadIdx.x & 31;
    const int gw    = blockIdx.x * 4 + (threadIdx.x >> 5);
    const int strip = gw & 1;
    const int band  = (gw >> 1) & (BANDS - 1);
    const int p     = gw >> 6;
    const int rbase = band * RB;
    const int cb    = strip * 256 + lane * 8;     // first owned column (halfs)
    const int b     = p & 31;

    const float* chan = (p < 32 ? pred : tru) + (size_t)(2 * b + 1) * PLANE;
    const float* oth  = (p < 32 ? tru : pred) + (size_t)(2 * b + 1) * PLANE;
    const size_t off  = (size_t)p * PLANE;
    const __half* srcH; __half* dstH;
    if (it & 1) { srcH = g_bufA + off; dstH = g_bufB + off; }
    else        { srcH = g_bufB + off; dstH = g_bufA + off; }

    const bool eL = (lane == 0  && strip == 1);   // halo LDG cols 252-255
    const bool eR = (lane == 31 && strip == 0);   // halo LDG cols 256-259

    float accC = 0.f, accS = 0.f;
    if (band == 0 || band == BANDS - 1)
        fused_core<MODE, true >(lane, rbase, cb, eL, eR, chan, srcH, dstH, oth, accC, accS);
    else
        fused_core<MODE, false>(lane, rbase, cb, eL, eR, chan, srcH, dstH, oth, accC, accS);

    if (MODE == 2) {
#pragma unroll
        for (int s = 16; s; s >>= 1) {
            accC += __shfl_xor_sync(0xffffffffu, accC, s);
            accS += __shfl_xor_sync(0xffffffffu, accS, s);
        }
        __shared__ float sC[4], sS[4];
        const int wi = threadIdx.x >> 5;
        if (lane == 0) { sC[wi] = accC; sS[wi] = accS; }
        __syncthreads();
        if (threadIdx.x == 0) {
            double c = (double)sC[0] + sC[1] + sC[2] + sC[3];
            double s = (double)sS[0] + sS[1] + sS[2] + sS[3];
            const int base = (p < 32) ? 0 : 2;   // p constant within block
            atomicAdd(&g_acc[base],     c);
            atomicAdd(&g_acc[base + 1], s);
        }
    }
}

__global__ void zero_acc()
{
    if (threadIdx.x < 4) g_acc[threadIdx.x] = 0.0;
}

__global__ void finalize_kernel(float* out)
{
    const double SMOOTH = 1.0;
    double tprec = (g_acc[0] + SMOOTH) / (g_acc[1] + SMOOTH);
    double tsens = (g_acc[2] + SMOOTH) / (g_acc[3] + SMOOTH);
    out[0] = (float)(1.0 - 2.0 * (tprec * tsens) / (tprec + tsens));
}

extern "C" void kernel_launch(void* const* d_in, const int* in_sizes, int n_in,
                              void* d_out, int out_size)
{
    const float* pred = (const float*)d_in[0];
    const float* tru  = (const float*)d_in[1];

    zero_acc<<<1, 32>>>();
    skel2_kernel<0><<<NBLOCKS, 128>>>(pred, tru, 0);  // iters 0,1 -> bufA
    skel2_kernel<1><<<NBLOCKS, 128>>>(pred, tru, 1);  // iters 2,3 A->B
    skel2_kernel<1><<<NBLOCKS, 128>>>(pred, tru, 2);  // iters 4,5 B->A
    skel2_kernel<1><<<NBLOCKS, 128>>>(pred, tru, 3);  // iters 6,7 A->B
    skel2_kernel<2><<<NBLOCKS, 128>>>(pred, tru, 4);  // iters 8,9 B->reduce
    finalize_kernel<<<1, 1>>>((float*)d_out);
}

// round 10
// speedup vs baseline: 1.4553x; 1.4553x over previous
#include <cuda_runtime.h>
#include <cuda_fp16.h>

typedef unsigned int u32;

#define H 512
#define W 512
#define PLANE (H * W)
#define NPLANES 64          // 32 pred + 32 true planes (channel 1 only)
#define RB 8                // output rows per warp
#define BANDS (H / RB)      // 64
#define KSTEPS (RB + 4)     // 12 pipeline steps
#define NBLOCKS (NPLANES * BANDS * 2 / 4)   // 2048 blocks of 128 thr
#define SROW 136            // u32 per staged row (544 B): [3]=Lhalo [4..131]=data [132]=Rhalo

#define PINF2 0x7C007C00u
#define NINF2 0xFC00FC00u

__device__ __half g_bufA[(size_t)NPLANES * PLANE];   // 32 MB
__device__ __half g_bufB[(size_t)NPLANES * PLANE];   // 32 MB
__device__ double g_acc[4];  // cross_pred, sum_pred, cross_true, sum_true

__device__ __forceinline__ u32 h2min(u32 a, u32 b) {
    __half2 r = __hmin2(*reinterpret_cast<__half2*>(&a),
                        *reinterpret_cast<__half2*>(&b));
    return *reinterpret_cast<u32*>(&r);
}
__device__ __forceinline__ u32 h2max(u32 a, u32 b) {
    __half2 r = __hmax2(*reinterpret_cast<__half2*>(&a),
                        *reinterpret_cast<__half2*>(&b));
    return *reinterpret_cast<u32*>(&r);
}
__device__ __forceinline__ u32 h2sub(u32 a, u32 b) {
    __half2 r = __hsub2(*reinterpret_cast<__half2*>(&a),
                        *reinterpret_cast<__half2*>(&b));
    return *reinterpret_cast<u32*>(&r);
}
__device__ __forceinline__ u32 h2add(u32 a, u32 b) {
    __half2 r = __hadd2(*reinterpret_cast<__half2*>(&a),
                        *reinterpret_cast<__half2*>(&b));
    return *reinterpret_cast<u32*>(&r);
}
__device__ __forceinline__ u32 pk(float lo, float hi) {
    __half2 r = __floats2half2_rn(lo, hi);
    return *reinterpret_cast<u32*>(&r);
}
__device__ __forceinline__ float2 up(u32 v) {
    return __half22float2(*reinterpret_cast<__half2*>(&v));
}
__device__ __forceinline__ u32 mid(u32 a, u32 b) { return __byte_perm(a, b, 0x5432); }
__device__ __forceinline__ u32 swp(u32 a)        { return __byte_perm(a, a, 0x1032); }

// =====================================================================
// Shared compute step (R7-verbatim pipeline body operating on xn[6]):
// vmin pair -> hmin -> (EDGE row pad) -> hmax -> vmax pair -> z.
// =====================================================================
struct PipeState {
    u32 xprev[6], xpair[6];
    u32 xc1[4], xc2[4], mcp[4];
    u32 hmp[4], hmpair[4];
    __device__ __forceinline__ void init() {
#pragma unroll
        for (int i = 0; i < 6; ++i) { xprev[i] = PINF2; xpair[i] = PINF2; }
#pragma unroll
        for (int i = 0; i < 4; ++i) {
            xc1[i] = 0u; xc2[i] = 0u; mcp[i] = 0u;
            hmp[i] = NINF2; hmpair[i] = NINF2;
        }
    }
};

template <bool EDGE>
__device__ __forceinline__ void pipe_step(
    PipeState& st, const u32 xn[6], int rv, u32 z[4], bool emit)
{
    u32 v[6];
#pragma unroll
    for (int i = 0; i < 6; ++i) v[i] = h2min(st.xpair[i], xn[i]);
#pragma unroll
    for (int i = 0; i < 6; ++i) { st.xpair[i] = h2min(st.xprev[i], xn[i]); st.xprev[i] = xn[i]; }

    u32 p01 = mid(v[0], v[1]), p12 = mid(v[1], v[2]), p23 = mid(v[2], v[3]);
    u32 p34 = mid(v[3], v[4]), p45 = mid(v[4], v[5]);
    u32 m0 = h2min(h2min(swp(v[0]), v[0]), p01);
    u32 m1 = h2min(h2min(p01, v[1]), p12);
    u32 m2 = h2min(h2min(p12, v[2]), p23);
    u32 m3 = h2min(h2min(p23, v[3]), p34);
    u32 m4 = h2min(h2min(p34, v[4]), p45);
    u32 m5 = h2min(h2min(p45, v[5]), swp(v[5]));

    if (EDGE && (unsigned)rv >= H) {     // maxpool pads -inf for OOB rows
        m0 = m1 = m2 = m3 = m4 = m5 = NINF2;
    }

    u32 q01 = mid(m0, m1), q12 = mid(m1, m2), q23 = mid(m2, m3);
    u32 q34 = mid(m3, m4), q45 = mid(m4, m5);
    u32 hv0 = h2max(h2max(q01, m1), q12);
    u32 hv1 = h2max(h2max(q12, m2), q23);
    u32 hv2 = h2max(h2max(q23, m3), q34);
    u32 hv3 = h2max(h2max(q34, m4), q45);

    if (emit) {
        // z = relu(x_o - dil + m_o), dil = max(hmpair, hv)  (dil >= m always)
        z[0] = h2max(h2add(h2sub(st.xc2[0], h2max(st.hmpair[0], hv0)), st.mcp[0]), 0u);
        z[1] = h2max(h2add(h2sub(st.xc2[1], h2max(st.hmpair[1], hv1)), st.mcp[1]), 0u);
        z[2] = h2max(h2add(h2sub(st.xc2[2], h2max(st.hmpair[2], hv2)), st.mcp[2]), 0u);
        z[3] = h2max(h2add(h2sub(st.xc2[3], h2max(st.hmpair[3], hv3)), st.mcp[3]), 0u);
    }

    st.hmpair[0] = h2max(st.hmp[0], hv0); st.hmp[0] = hv0;
    st.hmpair[1] = h2max(st.hmp[1], hv1); st.hmp[1] = hv1;
    st.hmpair[2] = h2max(st.hmp[2], hv2); st.hmp[2] = hv2;
    st.hmpair[3] = h2max(st.hmp[3], hv3); st.hmp[3] = hv3;
    st.mcp[0] = m1; st.mcp[1] = m2; st.mcp[2] = m3; st.mcp[3] = m4;
#pragma unroll
    for (int i = 0; i < 4; ++i) { st.xc2[i] = st.xc1[i]; st.xc1[i] = xn[i + 1]; }
}

// =====================================================================
// MODE 0: fp32 strided input, register raw-ring + shuffles (R7 path).
// =====================================================================
template <bool EDGE>
__device__ __forceinline__ void reg_core0(
    int lane, int rbase, int cb, bool eL, bool eR,
    const float* __restrict__ chan, __half* __restrict__ dstH)
{
    u32 raw[4][4];
    u32 rawE[4];
    PipeState st; st.init();

    auto loadraw = [&](int r, int s) {
        u32 a1 = PINF2, a2 = PINF2, a3 = PINF2, a4 = PINF2, ae = PINF2;
        if (!EDGE || (unsigned)r < H) {
            const float* row = chan + (size_t)r * W + cb;
            float4 f0 = *reinterpret_cast<const float4*>(row);
            float4 f1 = *reinterpret_cast<const float4*>(row + 4);
            a1 = pk(f0.x, f0.y); a2 = pk(f0.z, f0.w);
            a3 = pk(f1.x, f1.y); a4 = pk(f1.z, f1.w);
            if (eL)      { float2 e = *reinterpret_cast<const float2*>(row - 2); ae = pk(e.x, e.y); }
            else if (eR) { float2 e = *reinterpret_cast<const float2*>(row + 8); ae = pk(e.x, e.y); }
        }
        raw[s][0] = a1; raw[s][1] = a2; raw[s][2] = a3; raw[s][3] = a4;
        rawE[s] = ae;
    };

    loadraw(rbase - 2, 0);
    loadraw(rbase - 1, 1);

#pragma unroll
    for (int k = 0; k < KSTEPS; ++k) {
        if (k < KSTEPS - 2) loadraw(rbase + k, (k + 2) & 3);

        u32 xn[6];
        {
            const int s = k & 3;
            u32 a1 = raw[s][0], a4 = raw[s][3];
            u32 a0 = __shfl_up_sync(0xffffffffu, a4, 1);
            u32 a5 = __shfl_down_sync(0xffffffffu, a1, 1);
            if (lane == 0)  a0 = eL ? rawE[s] : PINF2;
            if (lane == 31) a5 = eR ? rawE[s] : PINF2;
            xn[0] = a0; xn[1] = a1; xn[2] = raw[s][1];
            xn[3] = raw[s][2]; xn[4] = a4; xn[5] = a5;
        }

        u32 z[4];
        pipe_step<EDGE>(st, xn, rbase + k - 3, z, k >= 4);
        if (k >= 4) {
            const int o = rbase + k - 4;
            uint4 s4; s4.x = z[0]; s4.y = z[1]; s4.z = z[2]; s4.w = z[3];
            *reinterpret_cast<uint4*>(dstH + (size_t)o * W + cb) = s4;
        }
    }
}

// =====================================================================
// MODE 1/2: half input staged through a per-warp smem ring via cp.async.
// 6 slots, depth-3, one commit-group per step. No shuffles, no raw ring.
// =====================================================================
template <int MODE, bool EDGE>
__device__ __forceinline__ void smem_core(
    u32* __restrict__ swp, int lane, int rbase, int cb, bool eL, bool eR,
    const __half* __restrict__ srcH, __half* __restrict__ dstH,
    const float* __restrict__ oth, float& accC_, float& accS_)
{
    const u32 swa = (u32)__cvta_generic_to_shared(swp);
    PipeState st; st.init();
    float accC = 0.f, accS = 0.f;

    // init halo slots to +inf (boundary strips never overwrite them)
    if (lane < 6) {
        swp[lane * SROW + 3]   = PINF2;
        swp[lane * SROW + 132] = PINF2;
    }

    auto issue = [&](int r, int s) {
        if (!EDGE || (unsigned)r < H) {
            const __half* row = srcH + (size_t)r * W + cb;
            u32 d = swa + (u32)(s * SROW + 4 + 4 * lane) * 4u;
            asm volatile("cp.async.cg.shared.global [%0], [%1], 16;\n"
                         :: "r"(d), "l"(row));
            if (eL) {
                u32 dh = swa + (u32)(s * SROW + 3) * 4u;
                asm volatile("cp.async.ca.shared.global [%0], [%1], 4;\n"
                             :: "r"(dh), "l"(row - 2));
            } else if (eR) {
                u32 dh = swa + (u32)(s * SROW + 132) * 4u;
                asm volatile("cp.async.ca.shared.global [%0], [%1], 4;\n"
                             :: "r"(dh), "l"(row + 8));
            }
        } else {
            *reinterpret_cast<uint4*>(swp + s * SROW + 4 + 4 * lane) =
                make_uint4(PINF2, PINF2, PINF2, PINF2);
            if (lane == 0)  swp[s * SROW + 3]   = PINF2;
            if (lane == 31) swp[s * SROW + 132] = PINF2;
        }
        asm volatile("cp.async.commit_group;\n" ::);
    };

    issue(rbase - 2, 0);
    issue(rbase - 1, 1);
    issue(rbase    , 2);

#pragma unroll
    for (int k = 0; k < KSTEPS; ++k) {
        if (k <= KSTEPS - 4) {
            issue(rbase + k + 1, (k + 3) % 6);
        } else {
            asm volatile("cp.async.commit_group;\n" ::);  // keep group cadence
        }
        asm volatile("cp.async.wait_group 3;\n" ::);
        __syncwarp();

        // consume row rbase+k-2 from slot k%6 (halo read from neighbors' bytes)
        u32 xn[6];
        {
            const u32* sb = swp + (k % 6) * SROW + 4 * lane;
            xn[0] = sb[3];
            uint4 c = *reinterpret_cast<const uint4*>(sb + 4);
            xn[1] = c.x; xn[2] = c.y; xn[3] = c.z; xn[4] = c.w;
            xn[5] = sb[8];
        }

        u32 z[4];
        pipe_step<EDGE>(st, xn, rbase + k - 3, z, k >= 4);

        if (k >= 4) {
            const int o = rbase + k - 4;
            if (MODE == 2) {
                const float* orow = oth + (size_t)o * W + cb;
                float4 f0 = *reinterpret_cast<const float4*>(orow);
                float4 f1 = *reinterpret_cast<const float4*>(orow + 4);
                float2 a0 = up(z[0]), a1 = up(z[1]), a2 = up(z[2]), a3 = up(z[3]);
                accC += a0.x * f0.x + a0.y * f0.y + a1.x * f0.z + a1.y * f0.w;
                accC += a2.x * f1.x + a2.y * f1.y + a3.x * f1.z + a3.y * f1.w;
                accS += (a0.x + a0.y) + (a1.x + a1.y)
                      + (a2.x + a2.y) + (a3.x + a3.y);
            } else {
                uint4 s4; s4.x = z[0]; s4.y = z[1]; s4.z = z[2]; s4.w = z[3];
                *reinterpret_cast<uint4*>(dstH + (size_t)o * W + cb) = s4;
            }
        }
    }

    accC_ = accC;
    accS_ = accS;
}

// =====================================================================
// Kernels
// =====================================================================
__global__ void __launch_bounds__(128) skel0_kernel(
    const float* __restrict__ pred, const float* __restrict__ tru)
{
    const int lane  = threadIdx.x & 31;
    const int gw    = blockIdx.x * 4 + (threadIdx.x >> 5);
    const int strip = gw & 1;
    const int band  = (gw >> 1) & (BANDS - 1);
    const int p     = gw >> 7;
    const int rbase = band * RB;
    const int cb    = strip * 256 + lane * 8;
    const int b     = p & 31;

    const float* chan = (p < 32 ? pred : tru) + (size_t)(2 * b + 1) * PLANE;
    __half* dstH = g_bufA + (size_t)p * PLANE;   // it 0 writes bufA

    const bool eL = (lane == 0  && strip == 1);
    const bool eR = (lane == 31 && strip == 0);

    if (band == 0 || band == BANDS - 1)
        reg_core0<true >(lane, rbase, cb, eL, eR, chan, dstH);
    else
        reg_core0<false>(lane, rbase, cb, eL, eR, chan, dstH);
}

template <int MODE>
__global__ void __launch_bounds__(128, 10) skel_kernel(
    const float* __restrict__ pred, const float* __restrict__ tru, int it)
{
    __shared__ __align__(16) u32 stg[4][6 * SROW];   // 13 KB / block

    const int lane  = threadIdx.x & 31;
    const int wi    = threadIdx.x >> 5;
    const int gw    = blockIdx.x * 4 + wi;
    const int strip = gw & 1;
    const int band  = (gw >> 1) & (BANDS - 1);
    const int p     = gw >> 7;
    const int rbase = band * RB;
    const int cb    = strip * 256 + lane * 8;
    const int b     = p & 31;

    const float* oth  = (p < 32 ? tru : pred) + (size_t)(2 * b + 1) * PLANE;
    const size_t off  = (size_t)p * PLANE;
    const __half* srcH; __half* dstH;
    if (it & 1) { srcH = g_bufA + off; dstH = g_bufB + off; }
    else        { srcH = g_bufB + off; dstH = g_bufA + off; }

    const bool eL = (lane == 0  && strip == 1);
    const bool eR = (lane == 31 && strip == 0);

    float accC = 0.f, accS = 0.f;
    if (band == 0 || band == BANDS - 1)
        smem_core<MODE, true >(stg[wi], lane, rbase, cb, eL, eR, srcH, dstH, oth, accC, accS);
    else
        smem_core<MODE, false>(stg[wi], lane, rbase, cb, eL, eR, srcH, dstH, oth, accC, accS);

    if (MODE == 2) {
#pragma unroll
        for (int s = 16; s; s >>= 1) {
            accC += __shfl_xor_sync(0xffffffffu, accC, s);
            accS += __shfl_xor_sync(0xffffffffu, accS, s);
        }
        __shared__ float sC[4], sS[4];
        if (lane == 0) { sC[wi] = accC; sS[wi] = accS; }
        __syncthreads();
        if (threadIdx.x == 0) {
            double c = (double)sC[0] + sC[1] + sC[2] + sC[3];
            double s = (double)sS[0] + sS[1] + sS[2] + sS[3];
            const int base = (p < 32) ? 0 : 2;   // p constant within block
            atomicAdd(&g_acc[base],     c);
            atomicAdd(&g_acc[base + 1], s);
        }
    }
}

__global__ void zero_acc()
{
    if (threadIdx.x < 4) g_acc[threadIdx.x] = 0.0;
}

__global__ void finalize_kernel(float* out)
{
    const double SMOOTH = 1.0;
    double tprec = (g_acc[0] + SMOOTH) / (g_acc[1] + SMOOTH);
    double tsens = (g_acc[2] + SMOOTH) / (g_acc[3] + SMOOTH);
    out[0] = (float)(1.0 - 2.0 * (tprec * tsens) / (tprec + tsens));
}

extern "C" void kernel_launch(void* const* d_in, const int* in_sizes, int n_in,
                              void* d_out, int out_size)
{
    const float* pred = (const float*)d_in[0];
    const float* tru  = (const float*)d_in[1];

    zero_acc<<<1, 32>>>();
    skel0_kernel<<<NBLOCKS, 128>>>(pred, tru);             // it 0 -> bufA
    for (int it = 1; it < 9; ++it)
        skel_kernel<1><<<NBLOCKS, 128>>>(pred, tru, it);   // ping-pong
    skel_kernel<2><<<NBLOCKS, 128>>>(pred, tru, 9);        // + reduction
    finalize_kernel<<<1, 1>>>((float*)d_out);
}

// round 11
// speedup vs baseline: 1.5885x; 1.0915x over previous
#include <cuda_runtime.h>
#include <cuda_fp16.h>

typedef unsigned int u32;

#define H 512
#define W 512
#define PLANE (H * W)
#define NPLANES 64          // 32 pred + 32 true planes (channel 1 only)
#define RB 8                // output rows per warp
#define BANDS (H / RB)      // 64
#define KSTEPS (RB + 4)     // 12 pipeline steps
#define NBLOCKS (NPLANES * BANDS * 2 / 4)   // 2048 blocks of 128 thr
#define SROW 136            // u32 per staged row: [3]=Lhalo [4..131]=data [132]=Rhalo

#define PINF2 0x7C007C00u
#define NINF2 0xFC00FC00u

__device__ __half g_bufA[(size_t)NPLANES * PLANE];   // 32 MB
__device__ __half g_bufB[(size_t)NPLANES * PLANE];   // 32 MB
__device__ double g_acc[4];  // cross_pred, sum_pred, cross_true, sum_true

__device__ __forceinline__ u32 h2min(u32 a, u32 b) {
    __half2 r = __hmin2(*reinterpret_cast<__half2*>(&a),
                        *reinterpret_cast<__half2*>(&b));
    return *reinterpret_cast<u32*>(&r);
}
__device__ __forceinline__ u32 h2max(u32 a, u32 b) {
    __half2 r = __hmax2(*reinterpret_cast<__half2*>(&a),
                        *reinterpret_cast<__half2*>(&b));
    return *reinterpret_cast<u32*>(&r);
}
__device__ __forceinline__ u32 h2sub(u32 a, u32 b) {
    __half2 r = __hsub2(*reinterpret_cast<__half2*>(&a),
                        *reinterpret_cast<__half2*>(&b));
    return *reinterpret_cast<u32*>(&r);
}
__device__ __forceinline__ u32 h2add(u32 a, u32 b) {
    __half2 r = __hadd2(*reinterpret_cast<__half2*>(&a),
                        *reinterpret_cast<__half2*>(&b));
    return *reinterpret_cast<u32*>(&r);
}
__device__ __forceinline__ u32 pk(float lo, float hi) {
    __half2 r = __floats2half2_rn(lo, hi);
    return *reinterpret_cast<u32*>(&r);
}
__device__ __forceinline__ float2 up(u32 v) {
    return __half22float2(*reinterpret_cast<__half2*>(&v));
}
__device__ __forceinline__ u32 mid(u32 a, u32 b) { return __byte_perm(a, b, 0x5432); }
__device__ __forceinline__ u32 swp(u32 a)        { return __byte_perm(a, a, 0x1032); }

// =====================================================================
// Pipeline step (operates on xn[6] = 12 cols: halo +-2 around 8 owned):
// vmin pair -> hmin -> (EDGE row pad) -> hmax -> vmax pair -> z.
// =====================================================================
struct PipeState {
    u32 xprev[6], xpair[6];
    u32 xc1[4], xc2[4], mcp[4];
    u32 hmp[4], hmpair[4];
    __device__ __forceinline__ void init() {
#pragma unroll
        for (int i = 0; i < 6; ++i) { xprev[i] = PINF2; xpair[i] = PINF2; }
#pragma unroll
        for (int i = 0; i < 4; ++i) {
            xc1[i] = 0u; xc2[i] = 0u; mcp[i] = 0u;
            hmp[i] = NINF2; hmpair[i] = NINF2;
        }
    }
};

template <bool EDGE>
__device__ __forceinline__ void pipe_step(
    PipeState& st, const u32 xn[6], int rv, u32 z[4], bool emit)
{
    u32 v[6];
#pragma unroll
    for (int i = 0; i < 6; ++i) v[i] = h2min(st.xpair[i], xn[i]);
#pragma unroll
    for (int i = 0; i < 6; ++i) { st.xpair[i] = h2min(st.xprev[i], xn[i]); st.xprev[i] = xn[i]; }

    u32 p01 = mid(v[0], v[1]), p12 = mid(v[1], v[2]), p23 = mid(v[2], v[3]);
    u32 p34 = mid(v[3], v[4]), p45 = mid(v[4], v[5]);
    u32 m0 = h2min(h2min(swp(v[0]), v[0]), p01);
    u32 m1 = h2min(h2min(p01, v[1]), p12);
    u32 m2 = h2min(h2min(p12, v[2]), p23);
    u32 m3 = h2min(h2min(p23, v[3]), p34);
    u32 m4 = h2min(h2min(p34, v[4]), p45);
    u32 m5 = h2min(h2min(p45, v[5]), swp(v[5]));

    if (EDGE && (unsigned)rv >= H) {     // maxpool pads -inf for OOB rows
        m0 = m1 = m2 = m3 = m4 = m5 = NINF2;
    }

    u32 q01 = mid(m0, m1), q12 = mid(m1, m2), q23 = mid(m2, m3);
    u32 q34 = mid(m3, m4), q45 = mid(m4, m5);
    u32 hv0 = h2max(h2max(q01, m1), q12);
    u32 hv1 = h2max(h2max(q12, m2), q23);
    u32 hv2 = h2max(h2max(q23, m3), q34);
    u32 hv3 = h2max(h2max(q34, m4), q45);

    if (emit) {
        // z = relu(x_o - dil + m_o), dil = max(hmpair, hv)  (dil >= m always)
        z[0] = h2max(h2add(h2sub(st.xc2[0], h2max(st.hmpair[0], hv0)), st.mcp[0]), 0u);
        z[1] = h2max(h2add(h2sub(st.xc2[1], h2max(st.hmpair[1], hv1)), st.mcp[1]), 0u);
        z[2] = h2max(h2add(h2sub(st.xc2[2], h2max(st.hmpair[2], hv2)), st.mcp[2]), 0u);
        z[3] = h2max(h2add(h2sub(st.xc2[3], h2max(st.hmpair[3], hv3)), st.mcp[3]), 0u);
    }

    st.hmpair[0] = h2max(st.hmp[0], hv0); st.hmp[0] = hv0;
    st.hmpair[1] = h2max(st.hmp[1], hv1); st.hmp[1] = hv1;
    st.hmpair[2] = h2max(st.hmp[2], hv2); st.hmp[2] = hv2;
    st.hmpair[3] = h2max(st.hmp[3], hv3); st.hmp[3] = hv3;
    st.mcp[0] = m1; st.mcp[1] = m2; st.mcp[2] = m3; st.mcp[3] = m4;
#pragma unroll
    for (int i = 0; i < 4; ++i) { st.xc2[i] = st.xc1[i]; st.xc1[i] = xn[i + 1]; }
}

// =====================================================================
// MODE 0: fp32 strided input, register raw-ring + shuffles.
// =====================================================================
template <bool EDGE>
__device__ __forceinline__ void reg_core0(
    int lane, int rbase, int cb, bool eL, bool eR,
    const float* __restrict__ chan, __half* __restrict__ dstH)
{
    u32 raw[4][4];
    u32 rawE[4];
    PipeState st; st.init();

    auto loadraw = [&](int r, int s) {
        u32 a1 = PINF2, a2 = PINF2, a3 = PINF2, a4 = PINF2, ae = PINF2;
        if (!EDGE || (unsigned)r < H) {
            const float* row = chan + (size_t)r * W + cb;
            float4 f0 = *reinterpret_cast<const float4*>(row);
            float4 f1 = *reinterpret_cast<const float4*>(row + 4);
            a1 = pk(f0.x, f0.y); a2 = pk(f0.z, f0.w);
            a3 = pk(f1.x, f1.y); a4 = pk(f1.z, f1.w);
            if (eL)      { float2 e = *reinterpret_cast<const float2*>(row - 2); ae = pk(e.x, e.y); }
            else if (eR) { float2 e = *reinterpret_cast<const float2*>(row + 8); ae = pk(e.x, e.y); }
        }
        raw[s][0] = a1; raw[s][1] = a2; raw[s][2] = a3; raw[s][3] = a4;
        rawE[s] = ae;
    };

    loadraw(rbase - 2, 0);
    loadraw(rbase - 1, 1);

#pragma unroll
    for (int k = 0; k < KSTEPS; ++k) {
        if (k < KSTEPS - 2) loadraw(rbase + k, (k + 2) & 3);

        u32 xn[6];
        {
            const int s = k & 3;
            u32 a1 = raw[s][0], a4 = raw[s][3];
            u32 a0 = __shfl_up_sync(0xffffffffu, a4, 1);
            u32 a5 = __shfl_down_sync(0xffffffffu, a1, 1);
            if (lane == 0)  a0 = eL ? rawE[s] : PINF2;
            if (lane == 31) a5 = eR ? rawE[s] : PINF2;
            xn[0] = a0; xn[1] = a1; xn[2] = raw[s][1];
            xn[3] = raw[s][2]; xn[4] = a4; xn[5] = a5;
        }

        u32 z[4];
        pipe_step<EDGE>(st, xn, rbase + k - 3, z, k >= 4);
        if (k >= 4) {
            const int o = rbase + k - 4;
            uint4 s4; s4.x = z[0]; s4.y = z[1]; s4.z = z[2]; s4.w = z[3];
            *reinterpret_cast<uint4*>(dstH + (size_t)o * W + cb) = s4;
        }
    }
}

// =====================================================================
// MODE 1/2: half input staged through per-warp smem ring via cp.async.
// Double-buffered consume: slot k+1 is LDS'd during step k's compute,
// so neither the wait_group nor the LDS latency sits on the chain.
// =====================================================================
template <int MODE, bool EDGE>
__device__ __forceinline__ void smem_core(
    u32* __restrict__ swp, int lane, int rbase, int cb, bool eL, bool eR,
    const __half* __restrict__ srcH, __half* __restrict__ dstH,
    const float* __restrict__ oth, float& accC_, float& accS_)
{
    const u32 swa = (u32)__cvta_generic_to_shared(swp);
    PipeState st; st.init();
    float accC = 0.f, accS = 0.f;

    // init halo slots to +inf (boundary strips never overwrite them)
    if (lane < 6) {
        swp[lane * SROW + 3]   = PINF2;
        swp[lane * SROW + 132] = PINF2;
    }
    __syncwarp();

    // slot j holds row rbase-2+j (mod 6)
    auto issue = [&](int j) {
        const int r = rbase - 2 + j;
        const int s = j % 6;
        if (!EDGE || (unsigned)r < H) {
            const __half* row = srcH + (size_t)r * W + cb;
            u32 d = swa + (u32)(s * SROW + 4 + 4 * lane) * 4u;
            asm volatile("cp.async.cg.shared.global [%0], [%1], 16;\n"
                         :: "r"(d), "l"(row));
            if (eL) {
                u32 dh = swa + (u32)(s * SROW + 3) * 4u;
                asm volatile("cp.async.ca.shared.global [%0], [%1], 4;\n"
                             :: "r"(dh), "l"(row - 2));
            } else if (eR) {
                u32 dh = swa + (u32)(s * SROW + 132) * 4u;
                asm volatile("cp.async.ca.shared.global [%0], [%1], 4;\n"
                             :: "r"(dh), "l"(row + 8));
            }
        } else {
            *reinterpret_cast<uint4*>(swp + s * SROW + 4 + 4 * lane) =
                make_uint4(PINF2, PINF2, PINF2, PINF2);
            if (lane == 0)  swp[s * SROW + 3]   = PINF2;
            if (lane == 31) swp[s * SROW + 132] = PINF2;
        }
        asm volatile("cp.async.commit_group;\n" ::);
    };

    auto lds_row = [&](int j, u32 xn[6]) {
        const u32* sb = swp + (j % 6) * SROW + 4 * lane;
        xn[0] = sb[3];
        uint4 c = *reinterpret_cast<const uint4*>(sb + 4);
        xn[1] = c.x; xn[2] = c.y; xn[3] = c.z; xn[4] = c.w;
        xn[5] = sb[8];
    };

    issue(0); issue(1); issue(2); issue(3);      // rows rbase-2 .. rbase+1
    asm volatile("cp.async.wait_group 3;\n" ::); // slot 0 landed
    __syncwarp();
    u32 xn[6];
    lds_row(0, xn);

#pragma unroll
    for (int k = 0; k < KSTEPS; ++k) {
        // issue slot k+4 (depth-3 in flight); keep one group per step
        if (k + 4 < KSTEPS) issue(k + 4);
        else asm volatile("cp.async.commit_group;\n" ::);
        asm volatile("cp.async.wait_group 3;\n" ::);   // slot k+1 landed
        __syncwarp();

        u32 xn2[6];
        if (k + 1 < KSTEPS) lds_row(k + 1, xn2);   // prefetch next row's LDS

        u32 z[4];
        pipe_step<EDGE>(st, xn, rbase + k - 3, z, k >= 4);

        if (k >= 4) {
            const int o = rbase + k - 4;
            if (MODE == 2) {
                const float* orow = oth + (size_t)o * W + cb;
                float4 f0 = *reinterpret_cast<const float4*>(orow);
                float4 f1 = *reinterpret_cast<const float4*>(orow + 4);
                float2 a0 = up(z[0]), a1 = up(z[1]), a2 = up(z[2]), a3 = up(z[3]);
                accC += a0.x * f0.x + a0.y * f0.y + a1.x * f0.z + a1.y * f0.w;
                accC += a2.x * f1.x + a2.y * f1.y + a3.x * f1.z + a3.y * f1.w;
                accS += (a0.x + a0.y) + (a1.x + a1.y)
                      + (a2.x + a2.y) + (a3.x + a3.y);
            } else {
                uint4 s4; s4.x = z[0]; s4.y = z[1]; s4.z = z[2]; s4.w = z[3];
                *reinterpret_cast<uint4*>(dstH + (size_t)o * W + cb) = s4;
            }
        }

        if (k + 1 < KSTEPS) {
#pragma unroll
            for (int i = 0; i < 6; ++i) xn[i] = xn2[i];
        }
    }

    accC_ = accC;
    accS_ = accS;
}

// =====================================================================
// Kernels
// =====================================================================
__global__ void __launch_bounds__(128) skel0_kernel(
    const float* __restrict__ pred, const float* __restrict__ tru)
{
    // fold accumulator zeroing into iteration 0 (read by MODE2 much later)
    if (blockIdx.x == 0 && threadIdx.x < 4) g_acc[threadIdx.x] = 0.0;

    const int lane  = threadIdx.x & 31;
    const int gw    = blockIdx.x * 4 + (threadIdx.x >> 5);
    const int strip = gw & 1;
    const int band  = (gw >> 1) & (BANDS - 1);
    const int p     = gw >> 7;
    const int rbase = band * RB;
    const int cb    = strip * 256 + lane * 8;
    const int b     = p & 31;

    const float* chan = (p < 32 ? pred : tru) + (size_t)(2 * b + 1) * PLANE;
    __half* dstH = g_bufA + (size_t)p * PLANE;   // it 0 writes bufA

    const bool eL = (lane == 0  && strip == 1);
    const bool eR = (lane == 31 && strip == 0);

    if (band == 0 || band == BANDS - 1)
        reg_core0<true >(lane, rbase, cb, eL, eR, chan, dstH);
    else
        reg_core0<false>(lane, rbase, cb, eL, eR, chan, dstH);
}

template <int MODE>
__global__ void __launch_bounds__(128, 9) skel_kernel(
    const float* __restrict__ pred, const float* __restrict__ tru, int it)
{
    __shared__ __align__(16) u32 stg[4][6 * SROW];   // 13 KB / block

    const int lane  = threadIdx.x & 31;
    const int wi    = threadIdx.x >> 5;
    const int gw    = blockIdx.x * 4 + wi;
    const int strip = gw & 1;
    const int band  = (gw >> 1) & (BANDS - 1);
    const int p     = gw >> 7;
    const int rbase = band * RB;
    const int cb    = strip * 256 + lane * 8;
    const int b     = p & 31;

    const float* oth  = (p < 32 ? tru : pred) + (size_t)(2 * b + 1) * PLANE;
    const size_t off  = (size_t)p * PLANE;
    const __half* srcH; __half* dstH;
    if (it & 1) { srcH = g_bufA + off; dstH = g_bufB + off; }
    else        { srcH = g_bufB + off; dstH = g_bufA + off; }

    const bool eL = (lane == 0  && strip == 1);
    const bool eR = (lane == 31 && strip == 0);

    float accC = 0.f, accS = 0.f;
    if (band == 0 || band == BANDS - 1)
        smem_core<MODE, true >(stg[wi], lane, rbase, cb, eL, eR, srcH, dstH, oth, accC, accS);
    else
        smem_core<MODE, false>(stg[wi], lane, rbase, cb, eL, eR, srcH, dstH, oth, accC, accS);

    if (MODE == 2) {
#pragma unroll
        for (int s = 16; s; s >>= 1) {
            accC += __shfl_xor_sync(0xffffffffu, accC, s);
            accS += __shfl_xor_sync(0xffffffffu, accS, s);
        }
        __shared__ float sC[4], sS[4];
        if (lane == 0) { sC[wi] = accC; sS[wi] = accS; }
        __syncthreads();
        if (threadIdx.x == 0) {
            double c = (double)sC[0] + sC[1] + sC[2] + sC[3];
            double s = (double)sS[0] + sS[1] + sS[2] + sS[3];
            const int base = (p < 32) ? 0 : 2;   // p constant within block
            atomicAdd(&g_acc[base],     c);
            atomicAdd(&g_acc[base + 1], s);
        }
    }
}

__global__ void finalize_kernel(float* out)
{
    const double SMOOTH = 1.0;
    double tprec = (g_acc[0] + SMOOTH) / (g_acc[1] + SMOOTH);
    double tsens = (g_acc[2] + SMOOTH) / (g_acc[3] + SMOOTH);
    out[0] = (float)(1.0 - 2.0 * (tprec * tsens) / (tprec + tsens));
}

extern "C" void kernel_launch(void* const* d_in, const int* in_sizes, int n_in,
                              void* d_out, int out_size)
{
    const float* pred = (const float*)d_in[0];
    const float* tru  = (const float*)d_in[1];

    skel0_kernel<<<NBLOCKS, 128>>>(pred, tru);             // it 0 -> bufA (+acc zero)
    for (int it = 1; it < 9; ++it)
        skel_kernel<1><<<NBLOCKS, 128>>>(pred, tru, it);   // ping-pong
    skel_kernel<2><<<NBLOCKS, 128>>>(pred, tru, 9);        // + reduction
    finalize_kernel<<<1, 1>>>((float*)d_out);
}